// round 5
// baseline (speedup 1.0000x reference)
#include <cuda_runtime.h>

#define M_TOTAL 2048
#define IN_DIM  4096
#define OUT_DIM 4096
#define NB      16
#define RANK    16
#define BLK     256
#define NQ      4      // split-K quarters in kernelA
#define KA      64     // p's per quarter

typedef unsigned long long u64;

// Scratch (__device__ globals per allocation rules)
__device__ float g_T[NQ * NB * M_TOTAL * RANK];   // [qt][ib][m][r]  8 MB
__device__ float g_Z[NB * M_TOTAL * RANK];        // [o][m][r]       2 MB
__device__ float g_rsp[M_TOTAL * NB * NQ];        // [m][i*4+qt]

// ---------- f32x2 packed helpers ----------
__device__ __forceinline__ u64 pack2(float lo, float hi) {
    u64 r; asm("mov.b64 %0, {%1, %2};" : "=l"(r) : "f"(lo), "f"(hi)); return r;
}
__device__ __forceinline__ void unpack2(u64 p, float& lo, float& hi) {
    asm("mov.b64 {%0, %1}, %2;" : "=f"(lo), "=f"(hi) : "l"(p));
}
__device__ __forceinline__ void ffma2(u64& d, u64 a, u64 b) {
    asm("fma.rn.f32x2 %0, %1, %2, %0;" : "+l"(d) : "l"(a), "l"(b));
}

// ================= Kernel A: T_qt[m,i,r] = sum_{p in quarter} x*Vt =================
// f32x2 pairs run over the p (reduction) dimension -> no duplication movs.
#define ROWS_A  128
#define XSTR    68     // 64 + 4 pad floats; LDS.128 conflict-free (4*mg mod 32 distinct/8)

__global__ void __launch_bounds__(256)
kernelA(const float* __restrict__ x, const float* __restrict__ Vt)
{
    __shared__ float xs[ROWS_A * XSTR];        // 34.8 KB
    __shared__ u64   vts2[(KA / 2) * RANK];    // [p2][r] = (Vt[2p2][r], Vt[2p2+1][r]) 4 KB

    const int ib   = blockIdx.x >> 2;
    const int qt   = blockIdx.x & 3;
    const int row0 = blockIdx.y * ROWS_A;
    const int tid  = threadIdx.x;

    // Vt quarter, interleaved into p-pairs: thread -> (p2, r-pair)
    {
        int p2 = tid >> 3;          // 0..31
        int rp = tid & 7;           // r = 2rp, 2rp+1
        const float* vg = Vt + ((size_t)ib * BLK + qt * KA + 2 * p2) * RANK + 2 * rp;
        float2 a = *(const float2*)vg;
        float2 b = *(const float2*)(vg + RANK);
        vts2[p2 * 16 + 2 * rp]     = pack2(a.x, b.x);
        vts2[p2 * 16 + 2 * rp + 1] = pack2(a.y, b.y);
    }

    // x tile: 128 rows x 64 cols
    const float4* xg4 = (const float4*)x;
    #pragma unroll
    for (int idx = tid; idx < ROWS_A * 16; idx += 256) {
        int m  = idx >> 4;
        int c4 = idx & 15;
        ((float4*)(xs + m * XSTR))[c4] =
            xg4[(size_t)(row0 + m) * (IN_DIM / 4) + ib * 64 + qt * 16 + c4];
    }
    __syncthreads();

    const int mg = tid & 63;     // rows mg, mg+64
    const int rg = tid >> 6;     // 0..3 -> r = rg*4..rg*4+3 (warp-uniform => broadcast V)
    const float* xr0 = xs + mg * XSTR;
    const float* xr1 = xs + (mg + 64) * XSTR;

    u64 a0 = 0, a1 = 0, a2 = 0, a3 = 0;   // row mg,     r..r+3, pair-partial over p
    u64 b0 = 0, b1 = 0, b2 = 0, b3 = 0;   // row mg+64

    #pragma unroll 4
    for (int p4 = 0; p4 < 16; ++p4) {
        ulonglong2 xa = *(const ulonglong2*)(xr0 + p4 * 4);   // (p0,p1),(p2,p3)
        ulonglong2 xb = *(const ulonglong2*)(xr1 + p4 * 4);
        const u64* vp = vts2 + (2 * p4) * 16 + rg * 4;
        ulonglong2 v00 = *(const ulonglong2*)(vp);            // p2=2p4,  r..r+1
        ulonglong2 v01 = *(const ulonglong2*)(vp + 2);        // p2=2p4,  r+2..r+3
        ulonglong2 v10 = *(const ulonglong2*)(vp + 16);       // p2=2p4+1
        ulonglong2 v11 = *(const ulonglong2*)(vp + 18);
        ffma2(a0, xa.x, v00.x); ffma2(a1, xa.x, v00.y);
        ffma2(a2, xa.x, v01.x); ffma2(a3, xa.x, v01.y);
        ffma2(b0, xb.x, v00.x); ffma2(b1, xb.x, v00.y);
        ffma2(b2, xb.x, v01.x); ffma2(b3, xb.x, v01.y);
        ffma2(a0, xa.y, v10.x); ffma2(a1, xa.y, v10.y);
        ffma2(a2, xa.y, v11.x); ffma2(a3, xa.y, v11.y);
        ffma2(b0, xb.y, v10.x); ffma2(b1, xb.y, v10.y);
        ffma2(b2, xb.y, v11.x); ffma2(b3, xb.y, v11.y);
    }

    // Combine even/odd-p partials and store (coalesced: [qt][ib][m][r])
    float lo, hi; float4 t;
    float* gTq = g_T + (size_t)(qt * NB + ib) * (M_TOTAL * RANK);
    unpack2(a0, lo, hi); t.x = lo + hi;
    unpack2(a1, lo, hi); t.y = lo + hi;
    unpack2(a2, lo, hi); t.z = lo + hi;
    unpack2(a3, lo, hi); t.w = lo + hi;
    *(float4*)(gTq + (size_t)(row0 + mg) * RANK + rg * 4) = t;
    unpack2(b0, lo, hi); t.x = lo + hi;
    unpack2(b1, lo, hi); t.y = lo + hi;
    unpack2(b2, lo, hi); t.z = lo + hi;
    unpack2(b3, lo, hi); t.w = lo + hi;
    *(float4*)(gTq + (size_t)(row0 + mg + 64) * RANK + rg * 4) = t;

    // rowsum partials (xs unchanged since sync)
    if (tid < ROWS_A) {
        const float4* xr = (const float4*)(xs + tid * XSTR);
        float s = 0.f;
        #pragma unroll
        for (int c = 0; c < 16; ++c) {
            float4 v = xr[c];
            s += (v.x + v.y) + (v.z + v.w);
        }
        g_rsp[(size_t)(row0 + tid) * (NB * NQ) + ib * NQ + qt] = s;
    }
}

// ================= Kernel Z: Z[o][m][r] = sum_i T[m,i,r]*S[o,i,r] =================
#define ROWS_Z  16
#define TSTR    272

__global__ void __launch_bounds__(256)
kernelZ(const float* __restrict__ S)
{
    __shared__ float Ts[ROWS_Z * TSTR];
    __shared__ float Ss[NB * NB * RANK];

    const int row0 = blockIdx.x * ROWS_Z;
    const int tid  = threadIdx.x;

    #pragma unroll
    for (int i = tid; i < 1024; i += 256) ((float4*)Ss)[i] = ((const float4*)S)[i];

    // T layout [qt][i][m][r]; sum 4 quarters
    const float4* gT4 = (const float4*)g_T;
    #pragma unroll
    for (int idx = tid; idx < ROWS_Z * 64; idx += 256) {
        int i  = idx >> 6;
        int m  = (idx >> 2) & 15;
        int r4 = idx & 3;
        size_t base = ((size_t)i * M_TOTAL + row0 + m) * 4 + r4;
        const size_t qs = (size_t)NB * M_TOTAL * 4;
        float4 a = gT4[base];
        float4 b = gT4[base + qs];
        float4 c = gT4[base + 2 * qs];
        float4 d = gT4[base + 3 * qs];
        a.x += b.x + c.x + d.x; a.y += b.y + c.y + d.y;
        a.z += b.z + c.z + d.z; a.w += b.w + c.w + d.w;
        ((float4*)(Ts + m * TSTR + i * 16))[r4] = a;
    }
    __syncthreads();

    const int m = tid >> 4;
    const int r = tid & 15;

    float t[NB];
    #pragma unroll
    for (int i = 0; i < NB; ++i) t[i] = Ts[m * TSTR + i * 16 + r];

    #pragma unroll 4
    for (int o = 0; o < NB; ++o) {
        float z = 0.f;
        #pragma unroll
        for (int i = 0; i < NB; ++i) z = fmaf(t[i], Ss[o * 256 + i * 16 + r], z);
        g_Z[((size_t)o * M_TOTAL + row0 + m) * RANK + r] = z;
    }
}

// ================= Kernel B: out = Z @ U + (1+rowsum)*bias =================
#define ROWS_B  32
#define ZS2     33      // u64 stride for duplicated-Z smem

__global__ void __launch_bounds__(256)
kernelB(const float* __restrict__ U, const float* __restrict__ bias,
        float* __restrict__ out)
{
    __shared__ float Us[RANK * BLK];       // 16 KB
    __shared__ u64   Zt2[RANK * ZS2];      // (z,z) duplicated pairs, [r][m]
    __shared__ float rs[ROWS_B];

    const int o    = blockIdx.x;
    const int row0 = blockIdx.y * ROWS_B;
    const int tid  = threadIdx.x;

    const float4* Ug4 = (const float4*)(U + (size_t)o * (RANK * BLK));
    #pragma unroll
    for (int i = tid; i < 1024; i += 256) ((float4*)Us)[i] = Ug4[i];

    if (tid < 128) {
        int m  = tid >> 2;
        int rq = tid & 3;
        float4 z = ((const float4*)g_Z)[((size_t)o * M_TOTAL + row0 + m) * 4 + rq];
        Zt2[(rq * 4 + 0) * ZS2 + m] = pack2(z.x, z.x);
        Zt2[(rq * 4 + 1) * ZS2 + m] = pack2(z.y, z.y);
        Zt2[(rq * 4 + 2) * ZS2 + m] = pack2(z.z, z.z);
        Zt2[(rq * 4 + 3) * ZS2 + m] = pack2(z.w, z.w);
    }
    if (tid >= 128 && tid < 128 + ROWS_B) {
        int m = tid - 128;
        const float4* rp = (const float4*)(g_rsp + (size_t)(row0 + m) * (NB * NQ));
        float s = 1.0f;
        #pragma unroll
        for (int c = 0; c < 16; ++c) {
            float4 v = rp[c];
            s += (v.x + v.y) + (v.z + v.w);
        }
        rs[m] = s;
    }
    __syncthreads();

    const int mg = tid >> 5;        // 0..7 -> rows m0..m0+3
    const int qg = tid & 31;        // q = qg*4 and 128+qg*4
    const int m0 = mg * 4;

    const float4* b4 = (const float4*)bias;
    float4 ba = b4[o * 64 + qg];
    float4 bb = b4[o * 64 + 32 + qg];

    ulonglong2 Aa[4], Ab[4];
    #pragma unroll
    for (int j = 0; j < 4; ++j) {
        float r = rs[m0 + j];
        Aa[j].x = pack2(r * ba.x, r * ba.y);
        Aa[j].y = pack2(r * ba.z, r * ba.w);
        Ab[j].x = pack2(r * bb.x, r * bb.y);
        Ab[j].y = pack2(r * bb.z, r * bb.w);
    }

    #pragma unroll
    for (int r = 0; r < RANK; ++r) {
        const u64* zp = Zt2 + r * ZS2 + m0;
        u64 q0 = zp[0], q1 = zp[1], q2 = zp[2], q3 = zp[3];   // broadcast LDS.64
        ulonglong2 ua = *(const ulonglong2*)(Us + r * 256 + qg * 4);
        ulonglong2 ub = *(const ulonglong2*)(Us + r * 256 + 128 + qg * 4);
        ffma2(Aa[0].x, q0, ua.x); ffma2(Aa[0].y, q0, ua.y);
        ffma2(Ab[0].x, q0, ub.x); ffma2(Ab[0].y, q0, ub.y);
        ffma2(Aa[1].x, q1, ua.x); ffma2(Aa[1].y, q1, ua.y);
        ffma2(Ab[1].x, q1, ub.x); ffma2(Ab[1].y, q1, ub.y);
        ffma2(Aa[2].x, q2, ua.x); ffma2(Aa[2].y, q2, ua.y);
        ffma2(Ab[2].x, q2, ub.x); ffma2(Ab[2].y, q2, ub.y);
        ffma2(Aa[3].x, q3, ua.x); ffma2(Aa[3].y, q3, ua.y);
        ffma2(Ab[3].x, q3, ub.x); ffma2(Ab[3].y, q3, ub.y);
    }

    size_t ob = (size_t)(row0 + m0) * OUT_DIM + o * 256 + qg * 4;
    #pragma unroll
    for (int j = 0; j < 4; ++j) {
        *(ulonglong2*)(out + ob + (size_t)j * OUT_DIM)       = Aa[j];
        *(ulonglong2*)(out + ob + (size_t)j * OUT_DIM + 128) = Ab[j];
    }
}

extern "C" void kernel_launch(void* const* d_in, const int* in_sizes, int n_in,
                              void* d_out, int out_size)
{
    const float* x    = (const float*)d_in[0];
    const float* S    = (const float*)d_in[1];
    const float* U    = (const float*)d_in[2];
    const float* Vt   = (const float*)d_in[3];
    const float* bias = (const float*)d_in[4];
    float* out = (float*)d_out;

    kernelA<<<dim3(NB * NQ, M_TOTAL / ROWS_A), 256>>>(x, Vt);
    kernelZ<<<M_TOTAL / ROWS_Z, 256>>>(S);
    kernelB<<<dim3(NB, M_TOTAL / ROWS_B), 256>>>(U, bias, out);
}